// round 3
// baseline (speedup 1.0000x reference)
#include <cuda_runtime.h>
#include <cuda_bf16.h>
#include <math_constants.h>

// ---------------------------------------------------------------------------
// Dip statistic of a projected sample. Fully self-contained (no CUB).
//   1. proj = X @ p                  (matvec, warp per row)
//   2. bitonic sort of padded 2^18   (presort + 7 merge stages, in-place)
//   3. Hartigan dip on sorted        (single block; 2-thread hull builds,
//                                     block-parallel segment scans)
// Output: dip/(2N) as float32 scalar.
// All loops in the dip kernel are iteration-capped: a logic bug produces a
// wrong answer, never a GPU hang.
// ---------------------------------------------------------------------------

#define MAXN (1 << 18)   // 262144 >= N = 200000

__device__ float  g_proj[MAXN];       // projection, sorted in place
__device__ double g_xs[MAXN + 2];     // 1-based, xs[0] = 0
__device__ int    g_mn[MAXN + 2];
__device__ int    g_mj[MAXN + 2];
__device__ int    g_gcm[MAXN + 2];
__device__ int    g_lcm[MAXN + 2];

// ---------------------------------------------------------------------------
// Matvec: one warp per row, D = 128 (32 lanes x float4)
// ---------------------------------------------------------------------------
__global__ void matvec_kernel(const float* __restrict__ X,
                              const float* __restrict__ PV,
                              const int*   __restrict__ idx,
                              int N, int D)
{
    int gtid = blockIdx.x * blockDim.x + threadIdx.x;
    int warp = gtid >> 5;
    int lane = gtid & 31;
    if (warp >= N) return;

    const float* p = PV + (size_t)(*idx) * D;
    const float4* row = reinterpret_cast<const float4*>(X + (size_t)warp * D);
    const float4* p4  = reinterpret_cast<const float4*>(p);

    float4 a = row[lane];
    float4 b = p4[lane];
    float s = fmaf(a.x, b.x, fmaf(a.y, b.y, fmaf(a.z, b.z, a.w * b.w)));

    #pragma unroll
    for (int o = 16; o > 0; o >>= 1)
        s += __shfl_xor_sync(0xFFFFFFFFu, s, o);

    if (lane == 0) g_proj[warp] = s;
}

// Pad [N, MAXN) with +inf so it sorts to the tail.
__global__ void pad_kernel(int N)
{
    int i = N + blockIdx.x * blockDim.x + threadIdx.x;
    if (i < MAXN) g_proj[i] = CUDART_INF_F;
}

// ---------------------------------------------------------------------------
// Bitonic sort, in place over g_proj[0..MAXN).
// ---------------------------------------------------------------------------
__device__ __forceinline__ void cmpxchg(float& a, float& b, bool up)
{
    if (up ? (a > b) : (a < b)) { float t = a; a = b; b = t; }
}

// Sort each 2048-element tile; tile direction alternates with bit 11 of base.
__global__ void bitonic_presort_kernel()
{
    __shared__ float sh[2048];
    int base = blockIdx.x * 2048;
    int t = threadIdx.x;                 // 1024 threads
    sh[t]        = g_proj[base + t];
    sh[t + 1024] = g_proj[base + t + 1024];
    __syncthreads();

    bool asc = ((base & 2048) == 0);
    for (int size = 2; size <= 2048; size <<= 1) {
        for (int s = size >> 1; s > 0; s >>= 1) {
            int i = ((t & ~(s - 1)) << 1) | (t & (s - 1));
            int j = i | s;
            bool up = (((i & size) == 0) == asc);
            float a = sh[i], b = sh[j];
            cmpxchg(a, b, up);
            sh[i] = a; sh[j] = b;
            __syncthreads();
        }
    }
    g_proj[base + t]        = sh[t];
    g_proj[base + t + 1024] = sh[t + 1024];
}

// One global compare-exchange step of merge stage `size`, stride s >= 2048.
__global__ void bitonic_global_kernel(int size, int s)
{
    int t = blockIdx.x * blockDim.x + threadIdx.x;   // MAXN/2 threads
    int i = ((t & ~(s - 1)) << 1) | (t & (s - 1));
    int j = i | s;
    bool up = ((i & size) == 0);
    float a = g_proj[i], b = g_proj[j];
    cmpxchg(a, b, up);
    g_proj[i] = a; g_proj[j] = b;
}

// Finish merge stage `size` (>= 4096): strides 1024..1 in shared memory.
// Direction is constant per 2048-tile since size > 2048.
__global__ void bitonic_merge_shared_kernel(int size)
{
    __shared__ float sh[2048];
    int base = blockIdx.x * 2048;
    int t = threadIdx.x;
    sh[t]        = g_proj[base + t];
    sh[t + 1024] = g_proj[base + t + 1024];
    __syncthreads();

    bool up = ((base & size) == 0);
    for (int s = 1024; s > 0; s >>= 1) {
        int i = ((t & ~(s - 1)) << 1) | (t & (s - 1));
        int j = i | s;
        float a = sh[i], b = sh[j];
        cmpxchg(a, b, up);
        sh[i] = a; sh[j] = b;
        __syncthreads();
    }
    g_proj[base + t]        = sh[t];
    g_proj[base + t + 1024] = sh[t + 1024];
}

// ---------------------------------------------------------------------------
// Convert sorted float32 -> double, 1-based
// ---------------------------------------------------------------------------
__global__ void to_double_kernel(int N)
{
    int i = blockIdx.x * blockDim.x + threadIdx.x;
    if (i == 0) g_xs[0] = 0.0;
    if (i < N) g_xs[i + 1] = (double)g_proj[i];
}

// ---------------------------------------------------------------------------
// Dip kernel: single block of 256 threads.
// ---------------------------------------------------------------------------
__global__ void dip_kernel(int N, float* __restrict__ out)
{
    const double* __restrict__ xs = g_xs;
    const int tid = threadIdx.x;

    __shared__ int s_brk;
    __shared__ int s_ig, s_lgcm, s_ih, s_llcm;
    __shared__ double s_red[256];

    if (N < 4 || xs[1] == xs[N]) {
        if (tid == 0) out[0] = (float)(1.0 / (2.0 * (double)max(N, 1)));
        return;
    }

    // --- Phase 1: hull pointer builds (2 concurrent sequential threads) ---
    if (tid == 0) {
        g_mn[1] = 1;
        int    pm    = 1;
        double x_jm1 = xs[1];
        double x_pm  = xs[1];
        for (int j = 2; j <= N; j++) {
            double xj = xs[j];
            int    m   = j - 1;
            double xm  = x_jm1;
            int    mm  = pm;
            double xmm = x_pm;
            while (m != 1 &&
                   (xj - xm) * (double)(m - mm) >= (xm - xmm) * (double)(j - m)) {
                m = mm; xm = xmm;
                if (m != 1) { mm = g_mn[m]; xmm = xs[mm]; }
            }
            g_mn[j] = m;
            pm = m; x_pm = xm; x_jm1 = xj;
        }
    } else if (tid == 128) {
        g_mj[N] = N;
        int    pm    = N;
        double x_kp1 = xs[N];
        double x_pm  = xs[N];
        for (int k = N - 1; k >= 1; k--) {
            double xk = xs[k];
            int    m   = k + 1;
            double xm  = x_kp1;
            int    mm  = pm;
            double xmm = x_pm;
            while (m != N &&
                   (xk - xm) * (double)(m - mm) >= (xm - xmm) * (double)(k - m)) {
                m = mm; xm = xmm;
                if (m != N) { mm = g_mj[m]; xmm = xs[mm]; }
            }
            g_mj[k] = m;
            pm = m; x_pm = xm; x_kp1 = xk;
        }
    }
    __syncthreads();

    // --- Phase 2: outer loop (iteration-capped) ---------------------------
    int low = 1, high = N;
    double dip = 1.0;
    int ig0 = 0, ih0 = 0;

    for (int iter = 0; iter < 3000; iter++) {
        __syncthreads();   // separates prior bottom s_brk read from rewrites

        if (tid == 0) {
            g_gcm[1] = high;
            int i = 1;
            while (g_gcm[i] > low && i <= N) { g_gcm[i + 1] = g_mn[g_gcm[i]]; i++; }
            int ig = i, l_gcm = i, ix = i - 1;
            g_lcm[1] = low;
            i = 1;
            while (g_lcm[i] < high && i <= N) { g_lcm[i + 1] = g_mj[g_lcm[i]]; i++; }
            int ih = i, l_lcm = i, iv = 2;

            double d = 0.0;
            if (l_gcm != 2 || l_lcm != 2) {
                int cap = 3 * N + 10;
                do {
                    int gcmix = g_gcm[ix];
                    int lcmiv = g_lcm[iv];
                    if (gcmix > lcmiv) {
                        int gcmi1 = g_gcm[ix + 1];
                        double t = ((double)lcmiv - (double)gcmi1 + 1.0)
                                 - (xs[lcmiv] - xs[gcmi1]) * (double)(gcmix - gcmi1)
                                   / (xs[gcmix] - xs[gcmi1]);
                        iv++;
                        if (t >= d) { d = t; ig = ix + 1; ih = iv - 1; }
                    } else {
                        int lcmiv1 = g_lcm[iv - 1];
                        double t = (xs[gcmix] - xs[lcmiv1]) * (double)(lcmiv - lcmiv1)
                                   / (xs[lcmiv] - xs[lcmiv1])
                                 - ((double)gcmix - (double)lcmiv1 - 1.0);
                        ix--;
                        if (t > d) { d = t; ig = ix + 1; ih = iv; }
                    }
                    if (ix < 1) ix = 1;
                    if (iv > l_lcm) iv = l_lcm;
                } while (g_gcm[ix] != g_lcm[iv] && --cap > 0);
            } else {
                d = 1.0;
            }

            if (d < dip) {
                s_brk = 1;
            } else {
                s_brk = 0;
                s_ig = ig; s_lgcm = l_gcm; s_ih = ih; s_llcm = l_lcm;
                ig0 = ig; ih0 = ih;
            }
        }
        __syncthreads();
        if (s_brk) break;

        // ---- parallel segment max scans (only the max value matters) ----
        double lm = 1.0;

        if (s_lgcm > s_ig) {       // gcm chain: descending in j
            int lo = g_gcm[s_lgcm];
            int hi = g_gcm[s_ig];
            for (int pos = lo + tid; pos <= hi; pos += blockDim.x) {
                int a = s_ig, b = s_lgcm - 1;
                while (a < b) {
                    int mid = (a + b) >> 1;
                    if (g_gcm[mid + 1] <= pos) b = mid; else a = mid + 1;
                }
                int jb = g_gcm[a + 1];
                int je = g_gcm[a];
                if (je - jb > 1 && xs[je] != xs[jb]) {
                    double C = (double)(je - jb) / (xs[je] - xs[jb]);
                    double t = (double)(pos - jb + 1) - (xs[pos] - xs[jb]) * C;
                    if (t > lm) lm = t;
                }
            }
        }

        if (s_llcm > s_ih) {       // lcm chain: ascending in j
            int lo = g_lcm[s_ih];
            int hi = g_lcm[s_llcm];
            for (int pos = lo + tid; pos <= hi; pos += blockDim.x) {
                int a = s_ih, b = s_llcm - 1;
                while (a < b) {
                    int mid = (a + b + 1) >> 1;
                    if (g_lcm[mid] <= pos) a = mid; else b = mid - 1;
                }
                int jb = g_lcm[a];
                int je = g_lcm[a + 1];
                if (je - jb > 1 && xs[je] != xs[jb]) {
                    double C = (double)(je - jb) / (xs[je] - xs[jb]);
                    double t = (xs[pos] - xs[jb]) * C - ((double)(pos - jb) - 1.0);
                    if (t > lm) lm = t;
                }
            }
        }

        s_red[tid] = lm;
        __syncthreads();
        #pragma unroll
        for (int s = 128; s > 0; s >>= 1) {
            if (tid < s) s_red[tid] = fmax(s_red[tid], s_red[tid + s]);
            __syncthreads();
        }

        if (tid == 0) {
            double dip_new = s_red[0];
            if (dip < dip_new) dip = dip_new;
            int nlow = g_gcm[ig0], nhigh = g_lcm[ih0];
            if (low == nlow && high == nhigh) {
                s_brk = 1;
            } else {
                s_brk = 0;
                low = nlow; high = nhigh;
            }
        }
        __syncthreads();
        if (s_brk) break;
    }

    if (tid == 0) out[0] = (float)(dip / (2.0 * (double)N));
}

// ---------------------------------------------------------------------------
// Launch: pure kernel launches, no runtime API calls.
// ---------------------------------------------------------------------------
extern "C" void kernel_launch(void* const* d_in, const int* in_sizes, int n_in,
                              void* d_out, int out_size)
{
    const float* X   = (const float*)d_in[0];
    const float* PV  = (const float*)d_in[1];
    const int*   idx = (const int*)d_in[2];
    float*       out = (float*)d_out;

    const int D = 128;
    const int N = in_sizes[0] / D;

    // 1. projection + pad
    matvec_kernel<<<(N + 7) / 8, 256>>>(X, PV, idx, N, D);
    pad_kernel<<<(MAXN - N + 255) / 256, 256>>>(N);

    // 2. bitonic sort (in place on g_proj)
    bitonic_presort_kernel<<<MAXN / 2048, 1024>>>();
    for (int size = 4096; size <= MAXN; size <<= 1) {
        for (int s = size >> 1; s >= 2048; s >>= 1)
            bitonic_global_kernel<<<(MAXN / 2) / 256, 256>>>(size, s);
        bitonic_merge_shared_kernel<<<MAXN / 2048, 1024>>>(size);
    }

    // 3. to double (1-based)
    to_double_kernel<<<(N + 255) / 256, 256>>>(N);

    // 4. dip
    dip_kernel<<<1, 256>>>(N, out);
}

// round 4
// speedup vs baseline: 1.1349x; 1.1349x over previous
#include <cuda_runtime.h>
#include <cuda_bf16.h>
#include <math_constants.h>

// ---------------------------------------------------------------------------
// Dip statistic of a projected sample. Self-contained (no CUB).
//   1. proj = X @ p                  (matvec, warp per row)
//   2. bitonic sort of padded 2^18   (presort + 7 merge stages, in-place)
//   3. Hartigan dip on sorted        (single block; 2 serial hull builds with
//                                     fp32 fast-path + exact fp64 fallback,
//                                     block-parallel segment scans)
// Output: dip/(2N) as float32 scalar.
// ---------------------------------------------------------------------------

#define MAXN (1 << 18)   // 262144 >= N = 200000

__device__ float  g_proj[MAXN];       // projection, sorted in place
__device__ float  g_xf[MAXN + 2];     // 1-based float copy of sorted values
__device__ double g_xs[MAXN + 2];     // 1-based double copy, xs[0] = 0
__device__ int    g_mn[MAXN + 2];
__device__ int    g_mj[MAXN + 2];
__device__ int    g_gcm[MAXN + 2];
__device__ int    g_lcm[MAXN + 2];
__device__ int    g_stkA_i[MAXN + 2];
__device__ float  g_stkA_x[MAXN + 2];
__device__ int    g_stkB_i[MAXN + 2];
__device__ float  g_stkB_x[MAXN + 2];

// ---------------------------------------------------------------------------
// Matvec: one warp per row, D = 128 (32 lanes x float4)
// ---------------------------------------------------------------------------
__global__ void matvec_kernel(const float* __restrict__ X,
                              const float* __restrict__ PV,
                              const int*   __restrict__ idx,
                              int N, int D)
{
    int gtid = blockIdx.x * blockDim.x + threadIdx.x;
    int warp = gtid >> 5;
    int lane = gtid & 31;
    if (warp >= N) return;

    const float* p = PV + (size_t)(*idx) * D;
    const float4* row = reinterpret_cast<const float4*>(X + (size_t)warp * D);
    const float4* p4  = reinterpret_cast<const float4*>(p);

    float4 a = row[lane];
    float4 b = p4[lane];
    float s = fmaf(a.x, b.x, fmaf(a.y, b.y, fmaf(a.z, b.z, a.w * b.w)));

    #pragma unroll
    for (int o = 16; o > 0; o >>= 1)
        s += __shfl_xor_sync(0xFFFFFFFFu, s, o);

    if (lane == 0) g_proj[warp] = s;
}

__global__ void pad_kernel(int N)
{
    int i = N + blockIdx.x * blockDim.x + threadIdx.x;
    if (i < MAXN) g_proj[i] = CUDART_INF_F;
}

// ---------------------------------------------------------------------------
// Bitonic sort, in place over g_proj[0..MAXN).
// ---------------------------------------------------------------------------
__device__ __forceinline__ void cmpxchg(float& a, float& b, bool up)
{
    if (up ? (a > b) : (a < b)) { float t = a; a = b; b = t; }
}

__global__ void bitonic_presort_kernel()
{
    __shared__ float sh[2048];
    int base = blockIdx.x * 2048;
    int t = threadIdx.x;                 // 1024 threads
    sh[t]        = g_proj[base + t];
    sh[t + 1024] = g_proj[base + t + 1024];
    __syncthreads();

    bool asc = ((base & 2048) == 0);
    for (int size = 2; size <= 2048; size <<= 1) {
        for (int s = size >> 1; s > 0; s >>= 1) {
            int i = ((t & ~(s - 1)) << 1) | (t & (s - 1));
            int j = i | s;
            bool up = (((i & size) == 0) == asc);
            float a = sh[i], b = sh[j];
            cmpxchg(a, b, up);
            sh[i] = a; sh[j] = b;
            __syncthreads();
        }
    }
    g_proj[base + t]        = sh[t];
    g_proj[base + t + 1024] = sh[t + 1024];
}

__global__ void bitonic_global_kernel(int size, int s)
{
    int t = blockIdx.x * blockDim.x + threadIdx.x;   // MAXN/2 threads
    int i = ((t & ~(s - 1)) << 1) | (t & (s - 1));
    int j = i | s;
    bool up = ((i & size) == 0);
    float a = g_proj[i], b = g_proj[j];
    cmpxchg(a, b, up);
    g_proj[i] = a; g_proj[j] = b;
}

__global__ void bitonic_merge_shared_kernel(int size)
{
    __shared__ float sh[2048];
    int base = blockIdx.x * 2048;
    int t = threadIdx.x;
    sh[t]        = g_proj[base + t];
    sh[t + 1024] = g_proj[base + t + 1024];
    __syncthreads();

    bool up = ((base & size) == 0);
    for (int s = 1024; s > 0; s >>= 1) {
        int i = ((t & ~(s - 1)) << 1) | (t & (s - 1));
        int j = i | s;
        float a = sh[i], b = sh[j];
        cmpxchg(a, b, up);
        sh[i] = a; sh[j] = b;
        __syncthreads();
    }
    g_proj[base + t]        = sh[t];
    g_proj[base + t + 1024] = sh[t + 1024];
}

// ---------------------------------------------------------------------------
// Convert sorted float32 -> double + float, 1-based
// ---------------------------------------------------------------------------
__global__ void to_double_kernel(int N)
{
    int i = blockIdx.x * blockDim.x + threadIdx.x;
    if (i == 0) { g_xs[0] = 0.0; g_xf[0] = 0.0f; g_xf[N + 1] = 0.0f; }
    if (i < N) {
        float v = g_proj[i];
        g_xs[i + 1] = (double)v;
        g_xf[i + 1] = v;
    }
}

// ---------------------------------------------------------------------------
// Pop test: pop iff (xa-xm)*(m-mm) >= (xm-xmm)*(a-m)   [reference semantics]
// fp32 fast path with conservative margin; exact fp64 fallback that matches
// the reference's float64 rounding bit-for-bit.
// ---------------------------------------------------------------------------
__device__ __forceinline__ bool pop_test(int a, float xa, int m, float xm,
                                         int mm, float xmm)
{
    float f1 = (xa - xm) * (float)(m - mm);
    float f2 = (xm - xmm) * (float)(a - m);
    float diff = f1 - f2;
    float margin = 1e-5f * (fabsf(f1) + fabsf(f2)) + 1e-30f;
    if (diff >  margin) return true;
    if (diff < -margin) return false;
    double p1 = ((double)xa - (double)xm) * (double)(m - mm);
    double p2 = ((double)xm - (double)xmm) * (double)(a - m);
    return p1 >= p2;
}

// ---------------------------------------------------------------------------
// Dip kernel: single block of 1024 threads.
//   Phase 1: tid 0 builds mn[] (left->right lower hull pointers),
//            tid 512 builds mj[] (right->left), register-cached stacks.
//   Phase 2: outer loop; tid 0 sequential chain, all threads segment scans.
// ---------------------------------------------------------------------------
__global__ void dip_kernel(int N, float* __restrict__ out)
{
    const double* __restrict__ xs = g_xs;
    const float*  __restrict__ xf = g_xf;
    const int tid = threadIdx.x;

    __shared__ int s_brk;
    __shared__ int s_ig, s_lgcm, s_ih, s_llcm;
    __shared__ double s_red[1024];

    if (N < 4 || xs[1] == xs[N]) {
        if (tid == 0) out[0] = (float)(1.0 / (2.0 * (double)max(N, 1)));
        return;
    }

    // --- Phase 1: hull pointer builds ------------------------------------
    if (tid == 0) {
        // mn[]: stack bottom = element 1 (never popped)
        int d = 0;                      // depth index of top
        int   top_i = 1;  float top_x = xf[1];
        int   bel_i = 0;  float bel_x = 0.0f;
        g_stkA_i[0] = 1; g_stkA_x[0] = top_x;
        float xn = xf[2];
        for (int j = 2; j <= N; j++) {
            float xj = xn; xn = xf[j + 1];      // prefetch
            while (d >= 1) {
                if (!pop_test(j, xj, top_i, top_x, bel_i, bel_x)) break;
                d--;
                top_i = bel_i; top_x = bel_x;
                if (d >= 1) { bel_i = g_stkA_i[d - 1]; bel_x = g_stkA_x[d - 1]; }
            }
            g_mn[j] = top_i;
            d++;
            g_stkA_i[d] = j; g_stkA_x[d] = xj;
            bel_i = top_i; bel_x = top_x;
            top_i = j;     top_x = xj;
        }
    } else if (tid == 512) {
        // mj[]: stack bottom = element N (never popped)
        int d = 0;
        int   top_i = N;  float top_x = xf[N];
        int   bel_i = 0;  float bel_x = 0.0f;
        g_stkB_i[0] = N; g_stkB_x[0] = top_x;
        float xn = xf[N - 1];
        for (int k = N - 1; k >= 1; k--) {
            float xk = xn; xn = xf[(k > 1) ? (k - 1) : 0];   // prefetch
            while (d >= 1) {
                if (!pop_test(k, xk, top_i, top_x, bel_i, bel_x)) break;
                d--;
                top_i = bel_i; top_x = bel_x;
                if (d >= 1) { bel_i = g_stkB_i[d - 1]; bel_x = g_stkB_x[d - 1]; }
            }
            g_mj[k] = top_i;
            d++;
            g_stkB_i[d] = k; g_stkB_x[d] = xk;
            bel_i = top_i; bel_x = top_x;
            top_i = k;     top_x = xk;
        }
    }
    __syncthreads();

    // --- Phase 2: outer loop (iteration-capped) ---------------------------
    int low = 1, high = N;
    double dip = 1.0;
    int ig0 = 0, ih0 = 0;

    for (int iter = 0; iter < 3000; iter++) {
        __syncthreads();   // separates prior bottom s_brk read from rewrites

        if (tid == 0) {
            g_gcm[1] = high;
            int i = 1;
            while (g_gcm[i] > low && i <= N) { g_gcm[i + 1] = g_mn[g_gcm[i]]; i++; }
            int ig = i, l_gcm = i, ix = i - 1;
            g_lcm[1] = low;
            i = 1;
            while (g_lcm[i] < high && i <= N) { g_lcm[i + 1] = g_mj[g_lcm[i]]; i++; }
            int ih = i, l_lcm = i, iv = 2;

            double d = 0.0;
            if (l_gcm != 2 || l_lcm != 2) {
                int cap = 3 * N + 10;
                do {
                    int gcmix = g_gcm[ix];
                    int lcmiv = g_lcm[iv];
                    if (gcmix > lcmiv) {
                        int gcmi1 = g_gcm[ix + 1];
                        double t = ((double)lcmiv - (double)gcmi1 + 1.0)
                                 - (xs[lcmiv] - xs[gcmi1]) * (double)(gcmix - gcmi1)
                                   / (xs[gcmix] - xs[gcmi1]);
                        iv++;
                        if (t >= d) { d = t; ig = ix + 1; ih = iv - 1; }
                    } else {
                        int lcmiv1 = g_lcm[iv - 1];
                        double t = (xs[gcmix] - xs[lcmiv1]) * (double)(lcmiv - lcmiv1)
                                   / (xs[lcmiv] - xs[lcmiv1])
                                 - ((double)gcmix - (double)lcmiv1 - 1.0);
                        ix--;
                        if (t > d) { d = t; ig = ix + 1; ih = iv; }
                    }
                    if (ix < 1) ix = 1;
                    if (iv > l_lcm) iv = l_lcm;
                } while (g_gcm[ix] != g_lcm[iv] && --cap > 0);
            } else {
                d = 1.0;
            }

            if (d < dip) {
                s_brk = 1;
            } else {
                s_brk = 0;
                s_ig = ig; s_lgcm = l_gcm; s_ih = ih; s_llcm = l_lcm;
                ig0 = ig; ih0 = ih;
            }
        }
        __syncthreads();
        if (s_brk) break;

        // ---- parallel segment max scans (only the max value matters) ----
        double lm = 1.0;

        if (s_lgcm > s_ig) {       // gcm chain: descending in j
            int lo = g_gcm[s_lgcm];
            int hi = g_gcm[s_ig];
            for (int pos = lo + tid; pos <= hi; pos += blockDim.x) {
                int a = s_ig, b = s_lgcm - 1;
                while (a < b) {
                    int mid = (a + b) >> 1;
                    if (g_gcm[mid + 1] <= pos) b = mid; else a = mid + 1;
                }
                int jb = g_gcm[a + 1];
                int je = g_gcm[a];
                if (je - jb > 1 && xs[je] != xs[jb]) {
                    double C = (double)(je - jb) / (xs[je] - xs[jb]);
                    double t = (double)(pos - jb + 1) - (xs[pos] - xs[jb]) * C;
                    if (t > lm) lm = t;
                }
            }
        }

        if (s_llcm > s_ih) {       // lcm chain: ascending in j
            int lo = g_lcm[s_ih];
            int hi = g_lcm[s_llcm];
            for (int pos = lo + tid; pos <= hi; pos += blockDim.x) {
                int a = s_ih, b = s_llcm - 1;
                while (a < b) {
                    int mid = (a + b + 1) >> 1;
                    if (g_lcm[mid] <= pos) a = mid; else b = mid - 1;
                }
                int jb = g_lcm[a];
                int je = g_lcm[a + 1];
                if (je - jb > 1 && xs[je] != xs[jb]) {
                    double C = (double)(je - jb) / (xs[je] - xs[jb]);
                    double t = (xs[pos] - xs[jb]) * C - ((double)(pos - jb) - 1.0);
                    if (t > lm) lm = t;
                }
            }
        }

        s_red[tid] = lm;
        __syncthreads();
        #pragma unroll
        for (int s = 512; s > 0; s >>= 1) {
            if (tid < s) s_red[tid] = fmax(s_red[tid], s_red[tid + s]);
            __syncthreads();
        }

        if (tid == 0) {
            double dip_new = s_red[0];
            if (dip < dip_new) dip = dip_new;
            int nlow = g_gcm[ig0], nhigh = g_lcm[ih0];
            if (low == nlow && high == nhigh) {
                s_brk = 1;
            } else {
                s_brk = 0;
                low = nlow; high = nhigh;
            }
        }
        __syncthreads();
        if (s_brk) break;
    }

    if (tid == 0) out[0] = (float)(dip / (2.0 * (double)N));
}

// ---------------------------------------------------------------------------
// Launch: pure kernel launches, no runtime API calls.
// ---------------------------------------------------------------------------
extern "C" void kernel_launch(void* const* d_in, const int* in_sizes, int n_in,
                              void* d_out, int out_size)
{
    const float* X   = (const float*)d_in[0];
    const float* PV  = (const float*)d_in[1];
    const int*   idx = (const int*)d_in[2];
    float*       out = (float*)d_out;

    const int D = 128;
    const int N = in_sizes[0] / D;

    // 1. projection + pad
    matvec_kernel<<<(N + 7) / 8, 256>>>(X, PV, idx, N, D);
    pad_kernel<<<(MAXN - N + 255) / 256, 256>>>(N);

    // 2. bitonic sort (in place on g_proj)
    bitonic_presort_kernel<<<MAXN / 2048, 1024>>>();
    for (int size = 4096; size <= MAXN; size <<= 1) {
        for (int s = size >> 1; s >= 2048; s >>= 1)
            bitonic_global_kernel<<<(MAXN / 2) / 256, 256>>>(size, s);
        bitonic_merge_shared_kernel<<<MAXN / 2048, 1024>>>(size);
    }

    // 3. to double/float (1-based)
    to_double_kernel<<<(N + 255) / 256, 256>>>(N);

    // 4. dip
    dip_kernel<<<1, 1024>>>(N, out);
}